// round 13
// baseline (speedup 1.0000x reference)
#include <cuda_runtime.h>

#define PH   8
#define NN   8
#define KK   64
#define CC   128
#define HH   128
#define WW   128
#define HW   (HH * WW)

#define CPB   8                  // channels per block
#define TPB   256                // one pair (2 positions) per thread; pairs <= 256
#define SROW  72                 // stage row stride (floats): 18 float4s max
#define SELEM (SROW * 18)        // 1296 floats per channel (<= 66x18 wide, 18x18 tall)

// One block: one (n,k) box, BOTH directions d=0/1, CPB channels.
// Phase 1: stage the box's sub-image into smem with aligned LDG.128 (xs
//   aligned down to 4; aligned float4 reads never cross the 128-px row end).
// Phase 2: R12 pair/mirror structure, but bilinear taps are LDS from the
//   stage (29-cyc latency, ~1 wavefront) instead of scattered LDG.
// d=1 plane is a pure linear mirror of d=0: phi(e) = (e<=C1) ? C1-e : e,
// C1 = (PH-1)*MW + width - 1 (block-uniform) -> divergence-free vector stores.

__global__ void __launch_bounds__(TPB)
bbp_kernel(const float* __restrict__ x,
           const float* __restrict__ boxes,
           float* __restrict__ feats,
           float* __restrict__ widths,
           int MW)
{
    __shared__ __align__(16) float S[CPB][SELEM];

    const int nk  = blockIdx.x;            // n*KK + k
    const int n   = nk >> 6;
    const int cc0 = blockIdx.y * CPB;
    const int tid = threadIdx.x;

    // ---- box parameters (uniform per block) ----
    const float4 b = reinterpret_cast<const float4*>(boxes)[nk];
    const float xmin = b.x, ymin = b.y, xmax = b.z, ymax = b.w;
    const bool valid_box = !(xmin == 0.f && ymin == 0.f && xmax == 0.f && ymax == 0.f);
    const float bwf = valid_box ? (xmax - xmin) : 1.f;
    const float bhf = valid_box ? (ymax - ymin) : 1.f;
    const bool wide = bwf > bhf;
    const float ratio = wide ? (bwf / bhf) : (bhf / bwf);
    const int   width = valid_box ? (int)ceilf(ratio * (float)PH) : 0;
    const float wf    = (float)(width > 2 ? width : 2);
    const float inv_wf1 = 1.0f / (wf - 1.0f);
    const float inv_ph1 = 1.0f / (float)(PH - 1);

    const int nij   = PH * MW;             // multiple of 8
    const int pairs = nij >> 1;            // <= 256

    if (tid == 0 && blockIdx.y == 0) {
        widths[(size_t)nk * 2 + 0] = (float)width;
        widths[(size_t)nk * 2 + 1] = (float)width;
    }

    const float* __restrict__ xbase = x + ((size_t)n * CC + cc0) * HW;

    // ---- phase 1: stage sub-image (uniform per block) ----
    int xs = 0, xe = 0, ys = 0, ye = 0, xs4 = 0;
    if (width > 0) {
        float pxmin, pxmax, pymin, pymax;
        if (wide) {
            pxmin = xmin; pxmax = xmin + (float)(width - 1) * bwf * inv_wf1;
            pymin = ymin; pymax = ymin + bhf;
        } else {
            pxmin = xmin; pxmax = xmin + bwf;
            pymin = ymin + (wf - (float)(width - 1)) * bhf * inv_wf1;
            pymax = ymin + wf * bhf * inv_wf1;   // documented one-step overshoot
        }
        xs = max(0, (int)floorf(pxmin - 0.5f));
        xe = min(WW - 1, (int)floorf(pxmax - 0.5f) + 1);
        ys = max(0, (int)floorf(pymin - 0.5f));
        ye = min(HH - 1, (int)floorf(pymax - 0.5f) + 1);
        xs4 = xs & ~3;                                  // aligned-down start
        const int nf4  = ((xe - xs4) >> 2) + 1;          // float4s per row (<=18)
        const int sh   = ye - ys + 1;                    // rows (<=18)
        const int cnt4 = nf4 * sh;                       // <=324
        const unsigned magic_f =
            (unsigned)((0x100000000ULL + (unsigned)nf4 - 1) / (unsigned)nf4);
        #pragma unroll
        for (int c = 0; c < CPB; ++c) {
            const float* __restrict__ xc = xbase + (size_t)c * HW;
            for (int t = tid; t < cnt4; t += TPB) {
                const int yy = (int)__umulhi((unsigned)t, magic_f);
                const int xx = t - yy * nf4;
                const float4 v4 = __ldg(reinterpret_cast<const float4*>(
                    xc + (ys + yy) * WW + xs4 + (xx << 2)));
                *reinterpret_cast<float4*>(&S[c][yy * SROW + (xx << 2)]) = v4;
            }
        }
    }
    __syncthreads();

    if (tid >= pairs) return;

    const int p  = tid << 1;                          // pair start (even)
    const int C1 = (PH - 1) * MW + width - 1;         // mirror constant

    // exact floor(pos/MW) for pos < 512 via magic multiply
    const unsigned magic = (unsigned)((0x100000000ULL + (unsigned)MW - 1) / (unsigned)MW);

    // ---- per-thread records for the 2 positions (offsets into stage) ----
    unsigned off_a[2];   // packed: off00 | off10<<16
    unsigned off_b[2];   // packed: off01 | off11<<16
    float4   wt[2];
    unsigned vmask = 0;

    #pragma unroll
    for (int s = 0; s < 2; ++s) {
        const int pos = p + s;
        const int i = (int)__umulhi((unsigned)pos, magic);
        const int j = pos - i * MW;
        off_a[s] = 0; off_b[s] = 0;
        wt[s] = make_float4(0.f, 0.f, 0.f, 0.f);
        if (j < width) {
            vmask |= (1u << s);
            float px, py;
            const float fi = (float)i, fj = (float)j;
            if (wide) {
                px = xmin + fj * bwf * inv_wf1;
                py = ymin + fi * bhf * inv_ph1;
            } else {
                px = xmin + fi * bwf * inv_ph1;
                py = ymin + (wf - fj) * bhf * inv_wf1;
            }
            const float ix = px - 0.5f;   // grid normalize/unnormalize cancels
            const float iy = py - 0.5f;
            const float x0f = floorf(ix), y0f = floorf(iy);
            const int x0 = (int)x0f, y0 = (int)y0f;
            const int x1 = x0 + 1,   y1 = y0 + 1;
            const float dx = ix - x0f, dy = iy - y0f;
            const float wx0 = 1.f - dx, wx1 = dx;
            const float wy0 = 1.f - dy, wy1 = dy;
            const bool vx0 = (x0 >= 0) & (x0 < WW);
            const bool vx1 = (x1 >= 0) & (x1 < WW);
            const bool vy0 = (y0 >= 0) & (y0 < HH);
            const bool vy1 = (y1 >= 0) & (y1 < HH);
            wt[s].x = (vx0 & vy0) ? wx0 * wy0 : 0.f;
            wt[s].y = (vx1 & vy0) ? wx1 * wy0 : 0.f;
            wt[s].z = (vx0 & vy1) ? wx0 * wy1 : 0.f;
            wt[s].w = (vx1 & vy1) ? wx1 * wy1 : 0.f;
            // clamp taps into the staged window (zero-weight taps land anywhere)
            const unsigned sx0 = (unsigned)(min(max(x0, xs), xe) - xs4);
            const unsigned sx1 = (unsigned)(min(max(x1, xs), xe) - xs4);
            const unsigned sy0 = (unsigned)(min(max(y0, ys), ye) - ys) * SROW;
            const unsigned sy1 = (unsigned)(min(max(y1, ys), ye) - ys) * SROW;
            off_a[s] = (sy0 + sx0) | ((sy0 + sx1) << 16);
            off_b[s] = (sy1 + sx0) | ((sy1 + sx1) << 16);
        }
    }

    // out1 addressing modes (region-uniform within the block)
    const bool tail = (p > C1);            // whole pair in padding tail (v==0)
    const bool mir  = (p + 1 <= C1);       // whole pair mirrored
    const bool oddC = ((C1 & 1) != 0);     // mirrored pairs 8B-aligned (block-uniform)

    float* __restrict__ f0 = feats + (((size_t)nk * 2 + 0) * CC + cc0) * nij;
    float* __restrict__ f1 = feats + (((size_t)nk * 2 + 1) * CC + cc0) * nij;

    #pragma unroll
    for (int c = 0; c < CPB; ++c) {
        float v0 = 0.f, v1 = 0.f;
        if (vmask & 1u) {
            v0 = wt[0].x * S[c][off_a[0] & 0xFFFFu]
               + wt[0].y * S[c][off_a[0] >> 16]
               + wt[0].z * S[c][off_b[0] & 0xFFFFu]
               + wt[0].w * S[c][off_b[0] >> 16];
        }
        if (vmask & 2u) {
            v1 = wt[1].x * S[c][off_a[1] & 0xFFFFu]
               + wt[1].y * S[c][off_a[1] >> 16]
               + wt[1].z * S[c][off_b[1] & 0xFFFFu]
               + wt[1].w * S[c][off_b[1] >> 16];
        }

        float* __restrict__ o0 = f0 + (size_t)c * nij;
        float* __restrict__ o1 = f1 + (size_t)c * nij;

        // d=0 plane: forward vector store (p even, plane base aligned)
        __stwt(reinterpret_cast<float2*>(o0 + p), make_float2(v0, v1));

        // d=1 plane via mirror phi
        if (tail) {
            __stwt(reinterpret_cast<float2*>(o1 + p), make_float2(0.f, 0.f));
        } else if (mir & oddC) {
            __stwt(reinterpret_cast<float2*>(o1 + (C1 - p - 1)),
                   make_float2(v1, v0));
        } else {
            const int a0 = (p     <= C1) ? (C1 - p)     : p;
            const int a1 = (p + 1 <= C1) ? (C1 - p - 1) : (p + 1);
            __stwt(o1 + a0, v0);
            __stwt(o1 + a1, v1);
        }
    }
}

extern "C" void kernel_launch(void* const* d_in, const int* in_sizes, int n_in,
                              void* d_out, int out_size)
{
    const float* x     = (const float*)d_in[0];
    const float* boxes = (const float*)d_in[1];
    float* out = (float*)d_out;

    // out = concat(feats (N,K,2,C,PH,MW), widths (N,K,2))
    const long long widths_elems = (long long)NN * KK * 2;               // 1024
    const long long per_mw       = (long long)NN * KK * 2 * CC * PH;     // 1048576
    int MW = (int)(((long long)out_size - widths_elems) / per_mw);
    if (MW < 1) MW = 1;
    if (MW > 64) MW = 64;   // nij <= 512 by construction (ratio < 8)

    float* feats  = out;
    float* widths = out + (size_t)per_mw * MW;

    dim3 grid(NN * KK, CC / CPB);
    bbp_kernel<<<grid, TPB>>>(x, boxes, feats, widths, MW);
}

// round 14
// speedup vs baseline: 1.3296x; 1.3296x over previous
#include <cuda_runtime.h>

#define PH   8
#define NN   8
#define KK   64
#define CC   128
#define HH   128
#define WW   128
#define HW   (HH * WW)

#define CSPLIT 16                // channel chunks per (n,k) box
#define CPB   (CC / CSPLIT)      // 8 channels per block
#define TPB   512                // one (i,j) record per thread (nij <= 512)

// Champion R3 structure: one block = one (n,k) box, BOTH directions d=0/1,
// CPB channels; one position per thread, record in registers, all 8 channel
// gathers batched (32 independent LDGs) then 16 coalesced stores.
// Change vs R3: default write-back stores (no __stwt/__stcs) so L2
// accumulates full 128B lines (incl. flip-plane reversed stores and width-
// boundary partials) and emits full-line DRAM writebacks.

__global__ void __launch_bounds__(TPB)
bbp_kernel(const float* __restrict__ x,
           const float* __restrict__ boxes,
           float* __restrict__ feats,
           float* __restrict__ widths,
           int MW)
{
    const int nk  = blockIdx.x;            // n*KK + k
    const int n   = nk >> 6;
    const int cc0 = blockIdx.y * CPB;
    const int tid = threadIdx.x;

    // ---- box parameters (uniform per block) ----
    const float4 b = reinterpret_cast<const float4*>(boxes)[nk];
    const float xmin = b.x, ymin = b.y, xmax = b.z, ymax = b.w;
    const bool valid_box = !(xmin == 0.f && ymin == 0.f && xmax == 0.f && ymax == 0.f);
    const float bwf = valid_box ? (xmax - xmin) : 1.f;
    const float bhf = valid_box ? (ymax - ymin) : 1.f;
    const bool wide = bwf > bhf;
    const float ratio = wide ? (bwf / bhf) : (bhf / bwf);
    const int   width = valid_box ? (int)ceilf(ratio * (float)PH) : 0;
    const float wf    = (float)(width > 2 ? width : 2);
    const float inv_wf1 = 1.0f / (wf - 1.0f);
    const float inv_ph1 = 1.0f / (float)(PH - 1);

    const int nij = PH * MW;
    const int e   = tid;

    if (tid == 0 && blockIdx.y == 0) {
        widths[(size_t)nk * 2 + 0] = (float)width;
        widths[(size_t)nk * 2 + 1] = (float)width;
    }
    if (e >= nij) return;

    // exact floor(e/MW) for e < 512 via magic multiply
    const unsigned magic = (unsigned)((0x100000000ULL + (unsigned)MW - 1) / (unsigned)MW);
    const int i = (int)__umulhi((unsigned)e, magic);
    const int j = e - i * MW;
    const bool val = (j < width);

    int4   off = make_int4(0, 0, 0, 0);
    float4 w   = make_float4(0.f, 0.f, 0.f, 0.f);
    int    dst1 = e;

    if (val) {
        dst1 = (PH - 1 - i) * MW + (width - 1 - j);
        float px, py;
        const float fi = (float)i, fj = (float)j;
        if (wide) {
            px = xmin + fj * bwf * inv_wf1;
            py = ymin + fi * bhf * inv_ph1;
        } else {
            px = xmin + fi * bwf * inv_ph1;
            py = ymin + (wf - fj) * bhf * inv_wf1;
        }
        const float ix = px - 0.5f;   // grid normalize/unnormalize cancels exactly
        const float iy = py - 0.5f;
        const float x0f = floorf(ix), y0f = floorf(iy);
        const int x0 = (int)x0f, y0 = (int)y0f;
        const int x1 = x0 + 1,   y1 = y0 + 1;
        const float dx = ix - x0f, dy = iy - y0f;
        const float wx0 = 1.f - dx, wx1 = dx;
        const float wy0 = 1.f - dy, wy1 = dy;
        const bool vx0 = (x0 >= 0) & (x0 < WW);
        const bool vx1 = (x1 >= 0) & (x1 < WW);
        const bool vy0 = (y0 >= 0) & (y0 < HH);
        const bool vy1 = (y1 >= 0) & (y1 < HH);
        w.x = (vx0 & vy0) ? wx0 * wy0 : 0.f;
        w.y = (vx1 & vy0) ? wx1 * wy0 : 0.f;
        w.z = (vx0 & vy1) ? wx0 * wy1 : 0.f;
        w.w = (vx1 & vy1) ? wx1 * wy1 : 0.f;
        const int xc0 = min(max(x0, 0), WW - 1);
        const int xc1 = min(max(x1, 0), WW - 1);
        const int yc0 = min(max(y0, 0), HH - 1);
        const int yc1 = min(max(y1, 0), HH - 1);
        off.x = yc0 * WW + xc0;
        off.y = yc0 * WW + xc1;
        off.z = yc1 * WW + xc0;
        off.w = yc1 * WW + xc1;
    }

    // ---- gather phase: all channels first (32 independent LDGs in flight) ----
    const float* __restrict__ xbase = x + ((size_t)n * CC + cc0) * HW;
    float* __restrict__ out0 = feats + (((size_t)nk * 2 + 0) * CC + cc0) * nij + e;
    float* __restrict__ out1 = feats + (((size_t)nk * 2 + 1) * CC + cc0) * nij + dst1;

    float v[CPB];
    if (val) {
        #pragma unroll
        for (int c = 0; c < CPB; ++c) {
            const float* __restrict__ xc = xbase + (size_t)c * HW;
            v[c] = w.x * __ldg(xc + off.x)
                 + w.y * __ldg(xc + off.y)
                 + w.z * __ldg(xc + off.z)
                 + w.w * __ldg(xc + off.w);
        }
    } else {
        #pragma unroll
        for (int c = 0; c < CPB; ++c) v[c] = 0.f;
    }

    // ---- store phase: default write-back stores, both planes coalesced ----
    #pragma unroll
    for (int c = 0; c < CPB; ++c) {
        out0[(size_t)c * nij] = v[c];   // straight
        out1[(size_t)c * nij] = v[c];   // flipped (or same-slot zero pad)
    }
}

extern "C" void kernel_launch(void* const* d_in, const int* in_sizes, int n_in,
                              void* d_out, int out_size)
{
    const float* x     = (const float*)d_in[0];
    const float* boxes = (const float*)d_in[1];
    float* out = (float*)d_out;

    // out = concat(feats (N,K,2,C,PH,MW), widths (N,K,2))
    const long long widths_elems = (long long)NN * KK * 2;               // 1024
    const long long per_mw       = (long long)NN * KK * 2 * CC * PH;     // 1048576
    int MW = (int)(((long long)out_size - widths_elems) / per_mw);
    if (MW < 1) MW = 1;
    if (MW > 64) MW = 64;   // nij <= 512 by construction (ratio < 8)

    float* feats  = out;
    float* widths = out + (size_t)per_mw * MW;

    dim3 grid(NN * KK, CSPLIT);
    bbp_kernel<<<grid, TPB>>>(x, boxes, feats, widths, MW);
}